// round 12
// baseline (speedup 1.0000x reference)
#include <cuda_runtime.h>

// out[r,c] = x[r,c] * scale[c],  scale[c] = (u[c] >= 0.1f) ? vec[c]/0.9f : 0
// x: [131072, 1024] fp32. DRAM-pinned stream (512 MB read + 512 MB write,
// ~6.8 TB/s measured ceiling). Proven-best structure: single fused kernel,
// float4 path, 8 elems/thread, exact-fit grid. R10 showed MLP 2->4 helped;
// this round: full front-batch (all 8 loads in flight before stores, MLP=8).

#define DEPTH 1024
#define P_DROP 0.1f

__global__ void __launch_bounds__(256)
fused_scale8_mlp8_kernel(const float4* __restrict__ x,
                         const float4* __restrict__ vec4,
                         const float4* __restrict__ u4,
                         float4* __restrict__ out) {
    int i = blockIdx.x * blockDim.x + threadIdx.x;
    const int S = gridDim.x * blockDim.x;   // 4,194,304 — multiple of 256

    // All 8 elements this thread touches share one column-quad.
    int c4 = i & (DEPTH / 4 - 1);
    float4 vv = __ldg(&vec4[c4]);           // 4 KB set: L1/L2 resident
    float4 uu = __ldg(&u4[c4]);
    const float r = 1.0f / (1.0f - P_DROP);
    float4 s;
    s.x = (uu.x >= P_DROP) ? vv.x * r : 0.0f;
    s.y = (uu.y >= P_DROP) ? vv.y * r : 0.0f;
    s.z = (uu.z >= P_DROP) ? vv.z * r : 0.0f;
    s.w = (uu.w >= P_DROP) ? vv.w * r : 0.0f;

    // Exact fit: all 8 independent loads issued before any store (MLP=8).
    float4 a[8];
#pragma unroll
    for (int k = 0; k < 8; k++) a[k] = x[i + k * S];

#pragma unroll
    for (int k = 0; k < 8; k++) {
        a[k].x *= s.x;
        a[k].y *= s.y;
        a[k].z *= s.z;
        a[k].w *= s.w;
    }

#pragma unroll
    for (int k = 0; k < 8; k++) out[i + k * S] = a[k];
}

extern "C" void kernel_launch(void* const* d_in, const int* in_sizes, int n_in,
                              void* d_out, int out_size) {
    const float* x   = (const float*)d_in[0];
    const float* vec = (const float*)d_in[1];
    const float* u   = (const float*)d_in[2];
    float* out = (float*)d_out;

    // n4 = out_size/4 = 33,554,432; 16384 blocks * 256 threads * 8 = n4 exactly.
    fused_scale8_mlp8_kernel<<<16384, 256>>>(
        (const float4*)x, (const float4*)vec, (const float4*)u, (float4*)out);
}